// round 6
// baseline (speedup 1.0000x reference)
#include <cuda_runtime.h>
#include <cuda_bf16.h>
#include <cstddef>

// B=64, S=512, D=768, max_sents=20 (segment id 20 is discarded).
#define BB 64
#define SS 512
#define DD 768
#define MS 20
#define M1 21
#define UNR 16
#define NT 192    // 192 threads x float4 = 768 = D

__global__ __launch_bounds__(NT)
void fused_kernel(const float* __restrict__ hidden,
                  const int* __restrict__ sent_ids,
                  float* __restrict__ out)
{
    const int b = blockIdx.x;
    const int k = blockIdx.y;
    const int col = threadIdx.x * 4;

    const float* hb = hidden + (size_t)b * SS * DD + col;

    if (k == MS) {   // doc CLS rep = hidden[b, 0, :]
        float4 v = __ldg(reinterpret_cast<const float4*>(hb));
        *reinterpret_cast<float4*>(out + (size_t)b * DD + col) = v;
        return;
    }

    __shared__ int rows_s[SS + UNR];
    __shared__ int n_s;

    // warp 0 builds the ascending row list for segment k via ballot compaction
    if (threadIdx.x < 32) {
        const int l = threadIdx.x;
        const int* sb = sent_ids + (size_t)b * SS;
        int base = 0;
        #pragma unroll
        for (int c = 0; c < SS / 32; c++) {
            int row = c * 32 + l;
            int id  = sb[row];
            unsigned m = __ballot_sync(0xffffffffu, id == k);
            if (id == k)
                rows_s[base + __popc(m & ((1u << l) - 1u))] = row;
            base += __popc(m);
        }
        if (l == 0) {
            int npad = (base + UNR - 1) & ~(UNR - 1);
            for (int i = base; i < npad; i++) rows_s[i] = 0;  // pad with row 0
            n_s = base;
        }
    }
    __syncthreads();

    const int n    = n_s;
    const int npad = (n + UNR - 1) & ~(UNR - 1);

    float4 a = make_float4(0.f, 0.f, 0.f, 0.f);

    for (int r = 0; r < npad; r += UNR) {
        int rw[UNR];
        #pragma unroll
        for (int u = 0; u < UNR; u++) rw[u] = rows_s[r + u];
        float4 v[UNR];
        #pragma unroll
        for (int u = 0; u < UNR; u++)
            v[u] = __ldcs(reinterpret_cast<const float4*>(hb + (size_t)rw[u] * DD));
        #pragma unroll
        for (int u = 0; u < UNR; u++) {
            a.x += v[u].x;  a.y += v[u].y;
            a.z += v[u].z;  a.w += v[u].w;
        }
    }

    // remove padding contribution (pad rows all point at row 0)
    if (npad != n) {
        float4 v0 = __ldg(reinterpret_cast<const float4*>(hb));
        float pad = (float)(npad - n);
        a.x -= pad * v0.x;  a.y -= pad * v0.y;
        a.z -= pad * v0.z;  a.w -= pad * v0.w;
    }

    const float inv = 1.0f / fmaxf((float)n, 1.0f);
    a.x *= inv;  a.y *= inv;  a.z *= inv;  a.w *= inv;

    float* sreps = out + (size_t)BB * DD;
    *reinterpret_cast<float4*>(
        sreps + ((size_t)b * MS + k) * DD + col) = a;
}

extern "C" void kernel_launch(void* const* d_in, const int* in_sizes, int n_in,
                              void* d_out, int out_size)
{
    const float* hidden   = (const float*)d_in[0];
    const int*   sent_ids = (const int*)d_in[1];
    float*       out      = (float*)d_out;

    dim3 grid(BB, M1);   // (64, 21) = 1344 blocks, single launch
    fused_kernel<<<grid, NT>>>(hidden, sent_ids, out);
}